// round 16
// baseline (speedup 1.0000x reference)
#include <cuda_runtime.h>
#include <cuda_bf16.h>
#include <cstdint>

typedef unsigned long long ull;

// ============ compile-time Cl(3,0,1) blade algebra ============
__host__ __device__ constexpr int pc4(int m){ return (m&1)+((m>>1)&1)+((m>>2)&1)+((m>>3)&1); }
__host__ __device__ constexpr int maskOf(int i){
  return i==0?0 : i==1?1 : i==2?2 : i==3?4 : i==4?8 : i==5?3 : i==6?5 : i==7?9 :
         i==8?6 : i==9?10 : i==10?12 : i==11?7 : i==12?11 : i==13?13 : i==14?14 : 15;
}
__host__ __device__ constexpr int idxOf(int m){
  return m==0?0 : m==1?1 : m==2?2 : m==4?3 : m==8?4 : m==3?5 : m==5?6 : m==9?7 :
         m==6?8 : m==10?9 : m==12?10 : m==7?11 : m==11?12 : m==13?13 : m==14?14 : 15;
}
__host__ __device__ constexpr int sperm(int a, int b){
  int s = 0;
  for (int i = 0; i < 4; ++i) if ((b>>i)&1) s += pc4(a >> (i+1));
  return (s&1) ? -1 : 1;
}
__host__ __device__ constexpr int gradeOf(int j){ return pc4(maskOf(j)); }
__host__ __device__ constexpr int pairOf(int j){ return (maskOf(j)&1) ? idxOf(maskOf(j)^1) : -1; }
__host__ __device__ constexpr int gpS(int j,int k){
  return (maskOf(j)&maskOf(k)&1) ? 0 : sperm(maskOf(j),maskOf(k));
}
__host__ __device__ constexpr int gpR(int j,int k){ return idxOf(maskOf(j)^maskOf(k)); }
__host__ __device__ constexpr int jnS(int j,int k){
  int b = maskOf(j), c = maskOf(k);
  if ((b|c) != 15) return 0;
  return sperm(b^c, 15^(b^c)) * sperm(15^b, 15^c) * sperm(b, 15^b) * sperm(c, 15^c);
}
__host__ __device__ constexpr int jnR(int j,int k){ return idxOf(15^(maskOf(j)^maskOf(k))); }

// ============ f32x2 packed primitives ============
__device__ __forceinline__ ull fma2(ull a, ull b, ull c){
  ull d; asm("fma.rn.f32x2 %0, %1, %2, %3;" : "=l"(d) : "l"(a), "l"(b), "l"(c)); return d;
}
__device__ __forceinline__ ull mul2(ull a, ull b){
  ull d; asm("mul.rn.f32x2 %0, %1, %2;" : "=l"(d) : "l"(a), "l"(b)); return d;
}
__device__ __forceinline__ ull neg2(ull a){ return a ^ 0x8000000080000000ull; }
__device__ __forceinline__ ull pk(float lo, float hi){
  ull r; asm("mov.b64 %0,{%1,%2};" : "=l"(r) : "f"(lo), "f"(hi)); return r;
}
__device__ __forceinline__ void upk(ull v, float& lo, float& hi){
  asm("mov.b64 {%0,%1},%2;" : "=f"(lo), "=f"(hi) : "l"(v));
}
__device__ __forceinline__ ull dupf(float x){
  unsigned u = __float_as_uint(x); return ((ull)u << 32) | (ull)u;
}
// load NQ ulonglong2 (16B) quads
template<int NQ>
__device__ __forceinline__ void ldq2(ull* d, const ull* p){
  #pragma unroll
  for (int q = 0; q < NQ; ++q){
    ulonglong2 v = *(const ulonglong2*)(p + 2*q);
    d[2*q] = v.x; d[2*q+1] = v.y;
  }
}

// fully-unrolled packed bilinears
template<int J, int K>
__device__ __forceinline__ void gp_k2(ull (&ga)[16], const ull (&L)[16], const ull (&R)[16]){
  if constexpr (K < 16){
    constexpr int s = gpS(J,K), r = gpR(J,K);
    if constexpr (s ==  1) ga[r] = fma2(L[J], R[K], ga[r]);
    if constexpr (s == -1) ga[r] = fma2(neg2(L[J]), R[K], ga[r]);
    gp_k2<J, K+1>(ga, L, R);
  }
}
template<int J>
__device__ __forceinline__ void gp_j2(ull (&ga)[16], const ull (&L)[16], const ull (&R)[16]){
  if constexpr (J < 16){ gp_k2<J,0>(ga, L, R); gp_j2<J+1>(ga, L, R); }
}
template<int J, int K>
__device__ __forceinline__ void jn_k2(ull (&ja)[16], const ull (&L)[16], const ull (&R)[16]){
  if constexpr (K < 16){
    constexpr int s = jnS(J,K), r = jnR(J,K);
    if constexpr (s ==  1) ja[r] = fma2(L[J], R[K], ja[r]);
    if constexpr (s == -1) ja[r] = fma2(neg2(L[J]), R[K], ja[r]);
    jn_k2<J, K+1>(ja, L, R);
  }
}
template<int J>
__device__ __forceinline__ void jn_j2(ull (&ja)[16], const ull (&L)[16], const ull (&R)[16]){
  if constexpr (J < 16){ jn_k2<J,0>(ja, L, R); jn_j2<J+1>(ja, L, R); }
}
// packed equi-linear step for one input channel
__device__ __forceinline__ void equi2(ull (&acc)[16], const ull (&xi)[16], const ull* w9){
  #pragma unroll
  for (int j = 0; j < 16; ++j){
    const int g = gradeOf(j);
    acc[j] = fma2(w9[g], xi[j], acc[j]);
    const int p = pairOf(j);
    if (p >= 0) acc[j] = fma2(w9[4+g], xi[p], acc[j]);
  }
}

// ============ sizes / layout ============
#define NTOK        32768
#define TOK_PER_BLK 64           // 32 token-pairs
#define NBLK        (NTOK / TOK_PER_BLK)
#define THREADS     512
#define XSTR        514          // xs row stride in ull: 16B/lane phase offsets -> conflict-free
#define SSTR        65
#define N_XS        (32*XSTR)
#define N_SS        (32*SSTR)
#define N_SCR       8192         // 512 threads x 16 ull ga spill
#define SMEM_BYTES  ((N_XS + N_SS + 32 + N_SCR)*8)

// ============ duplicated packed weights (prep kernel) ============
__device__ ull g_WLRd[16][32][20];  // [0..8]=dup wl, [10..18]=dup wr
__device__ ull g_WJd [16][32][20];  // jl / jr
__device__ ull g_WBd [16][32][20];  // wo_mv[2w] / wo_mv[2w+1]
__device__ ull g_WMSd[16][32][4];   // dup mvs2s[4w+q][c]
__device__ ull g_WS4d[16][64][4];   // dup {wl_s, wr_s, wjl_s, wjr_s}
__device__ ull g_WBSd[16][64][6];   // dup {s2mv[2w], s2mv[2w+1], s2s[4w..4w+3]}

__global__ void gb_prep(
    const float* __restrict__ wl_mv, const float* __restrict__ wl_s,
    const float* __restrict__ wr_mv, const float* __restrict__ wr_s,
    const float* __restrict__ wjl_mv, const float* __restrict__ wjl_s,
    const float* __restrict__ wjr_mv, const float* __restrict__ wjr_s,
    const float* __restrict__ wo_mv, const float* __restrict__ wo_s2mv,
    const float* __restrict__ wo_mvs2s, const float* __restrict__ wo_s2s)
{
  int tid = blockIdx.x * blockDim.x + threadIdx.x;
  if (tid < 16*32){
    int c = tid >> 5, i = tid & 31;
    for (int b = 0; b < 9; ++b){
      g_WLRd[c][i][b]    = dupf(wl_mv[(c*32+i)*9+b]);
      g_WLRd[c][i][10+b] = dupf(wr_mv[(c*32+i)*9+b]);
      g_WJd [c][i][b]    = dupf(wjl_mv[(c*32+i)*9+b]);
      g_WJd [c][i][10+b] = dupf(wjr_mv[(c*32+i)*9+b]);
      g_WBd [c][i][b]    = dupf(wo_mv[((2*c  )*32+i)*9+b]);
      g_WBd [c][i][10+b] = dupf(wo_mv[((2*c+1)*32+i)*9+b]);
    }
    g_WLRd[c][i][9]=0; g_WLRd[c][i][19]=0;
    g_WJd [c][i][9]=0; g_WJd [c][i][19]=0;
    g_WBd [c][i][9]=0; g_WBd [c][i][19]=0;
    for (int q = 0; q < 4; ++q) g_WMSd[c][i][q] = dupf(wo_mvs2s[(4*c+q)*32+i]);
  }
  if (tid < 16*64){
    int c = tid >> 6, s = tid & 63;
    g_WS4d[c][s][0] = dupf(wl_s [c*64+s]);
    g_WS4d[c][s][1] = dupf(wr_s [c*64+s]);
    g_WS4d[c][s][2] = dupf(wjl_s[c*64+s]);
    g_WS4d[c][s][3] = dupf(wjr_s[c*64+s]);
    g_WBSd[c][s][0] = dupf(wo_s2mv[(2*c  )*64+s]);
    g_WBSd[c][s][1] = dupf(wo_s2mv[(2*c+1)*64+s]);
    for (int q = 0; q < 4; ++q) g_WBSd[c][s][2+q] = dupf(wo_s2s[(4*c+q)*64+s]);
  }
}

// ============ main kernel ============
__global__ void __launch_bounds__(THREADS, 1) gb_main(
    const float* __restrict__ mv, const float* __restrict__ refmv,
    const float* __restrict__ sc, float* __restrict__ out_mv, float* __restrict__ out_s)
{
  extern __shared__ ull smu[];
  ull* xs    = smu;                 // [32 pairs][514]: paired x -> hidden -> out staging
  ull* ss    = smu + N_XS;          // [32][65]: paired scalars -> paired out_s
  ull* refs2 = ss + N_SS;           // [32]
  ull* scr   = refs2 + 32;          // [8192]: per-thread ga park
  const int tid = threadIdx.x;
  const int w = tid >> 5, lane = tid & 31;
  const long long t0 = (long long)blockIdx.x * TOK_PER_BLK;

  // ---- stage: pair-interleaved x/sc (tokens p and p+32 packed in one f32x2) ----
  #pragma unroll
  for (int pi = 0; pi < 2; ++pi){
    int p = w + pi*16;
    const float* lo = mv + (t0+p)*512;
    const float* hi = mv + (t0+32+p)*512;
    ull* row = xs + p*XSTR;
    #pragma unroll
    for (int k = 0; k < 8; ++k){
      int c = 2*lane + 64*k;
      float2 a = *(const float2*)(lo + c);
      float2 b = *(const float2*)(hi + c);
      ulonglong2 v; v.x = pk(a.x, b.x); v.y = pk(a.y, b.y);
      *(ulonglong2*)(row + c) = v;
    }
    const float* slo = sc + (t0+p)*64;
    const float* shi = sc + (t0+32+p)*64;
    ull* srow = ss + p*SSTR;
    srow[lane]    = pk(slo[lane],    shi[lane]);
    srow[lane+32] = pk(slo[lane+32], shi[lane+32]);
  }
  if (tid < 32) refs2[tid] = pk(refmv[(t0+tid)*16+15], refmv[(t0+32+tid)*16+15]);
  __syncthreads();

  const ull* xrow = xs + lane*XSTR;
  const ull* srow = ss + lane*SSTR;

  // ---- first-stage scalar biases (packed) ----
  ull bL2=0, bR2=0, bJL2=0, bJR2=0;
  #pragma unroll 4
  for (int s = 0; s < 64; ++s){
    ull sv = srow[s];
    ull w4[4]; ldq2<2>(w4, g_WS4d[w][s]);
    bL2  = fma2(w4[0], sv, bL2);  bR2  = fma2(w4[1], sv, bR2);
    bJL2 = fma2(w4[2], sv, bJL2); bJR2 = fma2(w4[3], sv, bJR2);
  }

  // ---- pass 1: left/right -> gp, park in scratch ----
  {
    ull L2[16], R2[16];
    #pragma unroll
    for (int j = 0; j < 16; ++j){ L2[j]=0; R2[j]=0; }
    L2[0]=bL2; R2[0]=bR2;
    #pragma unroll 2
    for (int i = 0; i < 32; ++i){
      ull xi2[16]; ldq2<8>(xi2, xrow + i*16);
      ull wb2[10];
      ldq2<5>(wb2, g_WLRd[w][i]);
      equi2(L2, xi2, wb2);
      ldq2<5>(wb2, g_WLRd[w][i] + 10);
      equi2(R2, xi2, wb2);
    }
    ull ga2[16];
    #pragma unroll
    for (int j = 0; j < 16; ++j) ga2[j]=0;
    gp_j2<0>(ga2, L2, R2);
    #pragma unroll
    for (int j = 0; j < 16; ++j) scr[j*THREADS + tid] = ga2[j];
  }

  // ---- pass 2: jl/jr -> join * ref15 ----
  ull ja2[16];
  {
    ull L2[16], R2[16];
    #pragma unroll
    for (int j = 0; j < 16; ++j){ L2[j]=0; R2[j]=0; }
    L2[0]=bJL2; R2[0]=bJR2;
    #pragma unroll 2
    for (int i = 0; i < 32; ++i){
      ull xi2[16]; ldq2<8>(xi2, xrow + i*16);
      ull wb2[10];
      ldq2<5>(wb2, g_WJd[w][i]);
      equi2(L2, xi2, wb2);
      ldq2<5>(wb2, g_WJd[w][i] + 10);
      equi2(R2, xi2, wb2);
    }
    #pragma unroll
    for (int j = 0; j < 16; ++j) ja2[j]=0;
    jn_j2<0>(ja2, L2, R2);
    ull r2 = refs2[lane];
    #pragma unroll
    for (int j = 0; j < 16; ++j) ja2[j] = mul2(ja2[j], r2);
  }

  // ---- write hidden (x dead) ----
  __syncthreads();
  {
    ull* hrow = xs + lane*XSTR;
    #pragma unroll
    for (int q = 0; q < 8; ++q){
      ulonglong2 g; g.x = scr[(2*q)*THREADS + tid]; g.y = scr[(2*q+1)*THREADS + tid];
      *(ulonglong2*)(hrow + w*16 + 2*q) = g;
      ulonglong2 j2; j2.x = ja2[2*q]; j2.y = ja2[2*q+1];
      *(ulonglong2*)(hrow + (16+w)*16 + 2*q) = j2;
    }
  }
  __syncthreads();

  // ---- phase B scalar part ----
  ull b0=0, b1=0, os0=0, os1=0, os2=0, os3=0;
  #pragma unroll 4
  for (int s = 0; s < 64; ++s){
    ull sv = srow[s];
    ull w6[6]; ldq2<3>(w6, g_WBSd[w][s]);
    b0  = fma2(w6[0], sv, b0);  b1  = fma2(w6[1], sv, b1);
    os0 = fma2(w6[2], sv, os0); os1 = fma2(w6[3], sv, os1);
    os2 = fma2(w6[4], sv, os2); os3 = fma2(w6[5], sv, os3);
  }

  // ---- phase B main: out channels 2w, 2w+1 ----
  ull A0[16], A1[16];
  #pragma unroll
  for (int j = 0; j < 16; ++j){ A0[j]=0; A1[j]=0; }
  A0[0]=b0; A1[0]=b1;
  const ull* hrow = xs + lane*XSTR;
  #pragma unroll 2
  for (int c = 0; c < 32; ++c){
    ull hi2[16]; ldq2<8>(hi2, hrow + c*16);
    ull wb2[10];
    ldq2<5>(wb2, g_WBd[w][c]);
    equi2(A0, hi2, wb2);
    ldq2<5>(wb2, g_WBd[w][c] + 10);
    equi2(A1, hi2, wb2);
  }
  // out_s from hidden[...,0]
  #pragma unroll 4
  for (int c = 0; c < 32; ++c){
    ull h0 = hrow[c*16];
    ull m4[4]; ldq2<2>(m4, g_WMSd[w][c]);
    os0 = fma2(m4[0], h0, os0); os1 = fma2(m4[1], h0, os1);
    os2 = fma2(m4[2], h0, os2); os3 = fma2(m4[3], h0, os3);
  }

  // ---- stage outputs, then coalesced stores ----
  __syncthreads();
  {
    ull* orow = xs + lane*XSTR;
    #pragma unroll
    for (int q = 0; q < 8; ++q){
      ulonglong2 v; v.x = A0[2*q]; v.y = A0[2*q+1];
      *(ulonglong2*)(orow + (2*w)*16 + 2*q) = v;
      ulonglong2 u; u.x = A1[2*q]; u.y = A1[2*q+1];
      *(ulonglong2*)(orow + (2*w+1)*16 + 2*q) = u;
    }
    ull* sro = ss + lane*SSTR;
    sro[4*w+0]=os0; sro[4*w+1]=os1; sro[4*w+2]=os2; sro[4*w+3]=os3;
  }
  __syncthreads();
  #pragma unroll
  for (int pi = 0; pi < 2; ++pi){
    int p = w + pi*16;
    float* lo = out_mv + (t0+p)*512;
    float* hi = out_mv + (t0+32+p)*512;
    const ull* row = xs + p*XSTR;
    #pragma unroll
    for (int k = 0; k < 8; ++k){
      int c = 2*lane + 64*k;
      ulonglong2 v = *(const ulonglong2*)(row + c);
      float l0,h0,l1,h1; upk(v.x, l0, h0); upk(v.y, l1, h1);
      *(float2*)(lo + c) = make_float2(l0, l1);
      *(float2*)(hi + c) = make_float2(h0, h1);
    }
    const ull* sro = ss + p*SSTR;
    { ull v = sro[lane];    float a,b; upk(v,a,b);
      out_s[(t0+p)*64+lane]    = a; out_s[(t0+32+p)*64+lane]    = b; }
    { ull v = sro[lane+32]; float a,b; upk(v,a,b);
      out_s[(t0+p)*64+lane+32] = a; out_s[(t0+32+p)*64+lane+32] = b; }
  }
}

// ============ launch ============
extern "C" void kernel_launch(void* const* d_in, const int* in_sizes, int n_in,
                              void* d_out, int out_size) {
  const float* mv    = (const float*)d_in[0];
  const float* refmv = (const float*)d_in[1];
  const float* sc    = (const float*)d_in[2];
  const float* wl_mv  = (const float*)d_in[6];
  const float* wl_s   = (const float*)d_in[7];
  const float* wr_mv  = (const float*)d_in[8];
  const float* wr_s   = (const float*)d_in[9];
  const float* wjl_mv = (const float*)d_in[10];
  const float* wjl_s  = (const float*)d_in[11];
  const float* wjr_mv = (const float*)d_in[12];
  const float* wjr_s  = (const float*)d_in[13];
  const float* wo_mv    = (const float*)d_in[14];
  const float* wo_s2mv  = (const float*)d_in[15];
  const float* wo_mvs2s = (const float*)d_in[16];
  const float* wo_s2s   = (const float*)d_in[17];

  float* out_mv = (float*)d_out;                       // (B,N,32,16)
  float* out_s  = out_mv + (long long)NTOK * 32 * 16;  // (B,N,64)

  gb_prep<<<2, 512>>>(wl_mv, wl_s, wr_mv, wr_s, wjl_mv, wjl_s, wjr_mv, wjr_s,
                      wo_mv, wo_s2mv, wo_mvs2s, wo_s2s);

  cudaFuncSetAttribute(gb_main, cudaFuncAttributeMaxDynamicSharedMemorySize, SMEM_BYTES);
  gb_main<<<NBLK, THREADS, SMEM_BYTES>>>(mv, refmv, sc, out_mv, out_s);
}